// round 15
// baseline (speedup 1.0000x reference)
#include <cuda_runtime.h>
#include <cuda_bf16.h>
#include <mma.h>
#include <cstdint>

using namespace nvcuda;

#define T_TOK 2048
#define H_DIM 2048
#define F_DIM 1024
#define NEXP  16
#define TOPK  4
#define NSLOT (T_TOK * TOPK)   // 8192

// ---------------- device scratch ----------------
__device__ int   g_cnt[NEXP];
__device__ int   g_slot[NEXP * NSLOT];
__device__ float g_wt[NEXP * NSLOT];
__device__ float g_part[(size_t)NSLOT * H_DIM];                    // 64 MB
__device__ __nv_bfloat16 g_wgu[(size_t)NEXP * 2 * F_DIM * H_DIM];  // 128 MB dequant
__device__ __nv_bfloat16 g_wdn[(size_t)NEXP * H_DIM * F_DIM];      // 64 MB dequant
__device__ __nv_bfloat16 g_xhi[(size_t)T_TOK * H_DIM];             // 8 MB
__device__ __nv_bfloat16 g_xlo[(size_t)T_TOK * H_DIM];             // 8 MB
__device__ __nv_bfloat16 g_ahi[(size_t)NSLOT * F_DIM];             // 16 MB
__device__ __nv_bfloat16 g_alo[(size_t)NSLOT * F_DIM];             // 16 MB

// resolved pointers: 0=x 1=ids 2=wts 3=guw 4=gus 5=dwn 6=dsc
__device__ const void* g_rp[7];
__device__ int g_bf[8];

struct InPtrs { const void* p[8]; long long sz[8]; int n; };

__device__ __forceinline__ float bfh(unsigned h) { return __uint_as_float(h << 16); }

// ---------------- content+dtype based input resolution (proven R8) ----------------
__global__ void k_resolve(InPtrs in) {
    __shared__ int cls[8], bff[8];
    __shared__ long long ssz[8];
    int w = threadIdx.x >> 5, lane = threadIdx.x & 31;
    if (w < 8 && lane == 0) { cls[w] = -1; bff[w] = 0; ssz[w] = 0; }
    __syncthreads();
    if (w < in.n && w < 8) {
        const unsigned* u = (const unsigned*)in.p[w];
        bool lt16 = true, i64ids = true, i64b = true, u32b = true;
        bool fint16 = true, fint256 = true;
        bool f32unit = true, f32mant0 = true, f32small = true;
        bool bfunit = true, bfpow2 = true, bfsmall = true;
        bool neg32 = false, pos32 = false, negB = false, posB = false;
        #pragma unroll
        for (int j = 0; j < 4; j++) {
            int idx = lane + 32 * j;
            unsigned v = u[idx];
            lt16   &= (v < 16u);
            i64ids &= (idx & 1) ? (v == 0u) : (v < 16u);
            i64b   &= (idx & 1) ? (v == 0u) : (v < 256u);
            u32b   &= (v < 256u);
            float f = __uint_as_float(v);
            unsigned ex = (v >> 23) & 255u;
            bool fin = (ex != 255u);
            bool isint = fin && f >= 0.f && f == floorf(f);
            fint16  &= (isint && f < 16.f);
            fint256 &= (isint && f < 256.f);
            f32unit  &= (fin && f > 0.f && f < 1.f);
            f32mant0 &= ((v & 0x7FFFFFu) == 0u);
            f32small &= (fin && fabsf(f) < 100.f);
            neg32 |= (f < 0.f); pos32 |= (f > 0.f);
            unsigned hs[2] = { v >> 16, v & 0xFFFFu };
            #pragma unroll
            for (int q = 0; q < 2; q++) {
                unsigned h = hs[q];
                float fb = bfh(h);
                bool finB = (((h >> 7) & 255u) != 255u);
                bfunit  &= (finB && fb > 0.f && fb < 1.f);
                bfpow2  &= (finB && fb > 0.f && fb < 1.f && ((h & 127u) == 0u));
                bfsmall &= (finB && fabsf(fb) < 100.f);
                negB |= (fb < 0.f); posB |= (fb > 0.f);
            }
        }
        unsigned full = ~0u;
        lt16 = __all_sync(full, lt16);       i64ids = __all_sync(full, i64ids);
        i64b = __all_sync(full, i64b);       u32b = __all_sync(full, u32b);
        fint16 = __all_sync(full, fint16);   fint256 = __all_sync(full, fint256);
        f32unit = __all_sync(full, f32unit); f32mant0 = __all_sync(full, f32mant0);
        f32small = __all_sync(full, f32small);
        bfunit = __all_sync(full, bfunit);   bfpow2 = __all_sync(full, bfpow2);
        bfsmall = __all_sync(full, bfsmall);
        neg32 = __any_sync(full, neg32);     pos32 = __any_sync(full, pos32);
        negB = __any_sync(full, negB);       posB = __any_sync(full, posB);
        if (lane == 0) {
            int c, bf = 0;
            if (lt16)                         { c = 0; }
            else if (i64ids)                  { c = 0; bf = 2; }
            else if (fint16)                  { c = 0; bf = 3; }
            else if (i64b)                    { c = 4; bf = 5; }
            else if (u32b)                    { c = 4; bf = 3; }
            else if (fint256)                 { c = 4; bf = 4; }
            else if (f32unit && f32mant0)     { c = 2; }
            else if (bfunit && bfpow2)        { c = 2; bf = 1; }
            else if (f32unit)                 { c = 1; }
            else if (bfunit)                  { c = 1; bf = 1; }
            else if (f32small && neg32 && pos32) { c = 3; }
            else if (bfsmall && negB && posB)    { c = 3; bf = 1; }
            else                              { c = 4; bf = 0; }
            cls[w] = c; bff[w] = bf; ssz[w] = in.sz[w];
        }
    }
    __syncthreads();
    if (threadIdx.x == 0) {
        int ix = -1, ii = -1, iw = -1, s1 = -1, s2 = -1, p1 = -1, p2 = -1;
        for (int i = 0; i < in.n && i < 8; i++) {
            switch (cls[i]) {
                case 0: ii = i; break;
                case 1: iw = i; break;
                case 2: if (s1 < 0) s1 = i; else s2 = i; break;
                case 3: ix = i; break;
                case 4: if (p1 < 0) p1 = i; else p2 = i; break;
                default: break;
            }
        }
        if (ix >= 0 && ii >= 0 && iw >= 0 && s2 >= 0 && p2 >= 0) {
            int gus_i = s1, dsc_i = s2;
            if (ssz[s2] > ssz[s1]) { gus_i = s2; dsc_i = s1; }
            int guw_i = p1, dwn_i = p2;
            if (ssz[p2] > ssz[p1]) { guw_i = p2; dwn_i = p1; }
            g_rp[0] = in.p[ix];    g_bf[0] = bff[ix];
            g_rp[1] = in.p[ii];    g_bf[1] = bff[ii];
            g_rp[2] = in.p[iw];    g_bf[2] = bff[iw];
            g_rp[3] = in.p[guw_i]; g_bf[3] = bff[guw_i];
            g_rp[4] = in.p[gus_i]; g_bf[4] = bff[gus_i];
            g_rp[5] = in.p[dwn_i]; g_bf[5] = bff[dwn_i];
            g_rp[6] = in.p[dsc_i]; g_bf[6] = bff[dsc_i];
            g_bf[7] = bff[ix];
        } else {
            g_rp[0] = in.p[0]; g_rp[2] = in.p[1]; g_rp[1] = in.p[2];
            g_rp[3] = in.p[3]; g_rp[4] = in.p[4]; g_rp[5] = in.p[5]; g_rp[6] = in.p[6];
            for (int i = 0; i < 8; i++) g_bf[i] = 0;
        }
        for (int e = 0; e < NEXP; e++) g_cnt[e] = 0;
    }
}

// ---------------- helpers ----------------
__device__ __forceinline__ float ldf(const void* p, int bf, size_t i) {
    return bf ? __bfloat162float(((const __nv_bfloat16*)p)[i]) : ((const float*)p)[i];
}
__device__ __forceinline__ int ldid(const void* p, int flag, int i) {
    if (flag == 2) return (int)((const long long*)p)[i];
    if (flag == 3) return (int)((const float*)p)[i];
    return ((const int*)p)[i];
}
__device__ __forceinline__ unsigned ldb(const void* p, int m, size_t i) {
    switch (m) {
        case 3:  return ((const unsigned*)p)[i] & 255u;
        case 4:  return (unsigned)((const float*)p)[i] & 255u;
        case 5:  return (unsigned)(((const unsigned long long*)p)[i] & 255ull);
        default: return ((const uint8_t*)p)[i];
    }
}
__device__ __forceinline__ float fp4v(unsigned n) {
    float m = (float)((0xC8643210u >> ((n & 7u) * 4)) & 15u);
    return (n & 8u) ? -m : m;
}
__device__ __forceinline__ uint32_t pack_bf2(float a, float b) {
    unsigned short ha = __bfloat16_as_ushort(__float2bfloat16(a));
    unsigned short hb = __bfloat16_as_ushort(__float2bfloat16(b));
    return (uint32_t)ha | ((uint32_t)hb << 16);
}
__device__ __forceinline__ uint32_t s2u(const void* p) {
    uint32_t a;
    asm("{ .reg .u64 t; cvta.to.shared.u64 t, %1; cvt.u32.u64 %0, t; }" : "=r"(a) : "l"(p));
    return a;
}
__device__ __forceinline__ void cp16(uint32_t saddr, const void* gaddr) {
    asm volatile("cp.async.cg.shared.global [%0], [%1], 16;" :: "r"(saddr), "l"(gaddr) : "memory");
}
__device__ __forceinline__ void cp_commit() {
    asm volatile("cp.async.commit_group;" ::: "memory");
}
template <int N>
__device__ __forceinline__ void cp_wait() {
    asm volatile("cp.async.wait_group %0;" :: "n"(N) : "memory");
}

// ---------------- one-time weight dequant to bf16 ----------------
__global__ void k_deq_gu() {
    size_t i = (size_t)blockIdx.x * 256 + threadIdx.x;
    const void* W = g_rp[3]; const int m = g_bf[3];
    const void* S = g_rp[4]; const int sbf = g_bf[4];
    size_t row = i >> 8;
    unsigned cb = ((unsigned)i & 255u) * 4u;
    float sc = ldf(S, sbf, row * 64 + (cb >> 4)) * 0.5f;
    float v[8];
    #pragma unroll
    for (int q = 0; q < 4; q++) {
        unsigned by = ldb(W, m, row * 1024 + cb + q);
        v[2 * q]     = fp4v(by & 15u) * sc;
        v[2 * q + 1] = fp4v(by >> 4)  * sc;
    }
    uint4 o = make_uint4(pack_bf2(v[0], v[1]), pack_bf2(v[2], v[3]),
                         pack_bf2(v[4], v[5]), pack_bf2(v[6], v[7]));
    ((uint4*)g_wgu)[i] = o;
}
__global__ void k_deq_dn() {
    size_t i = (size_t)blockIdx.x * 256 + threadIdx.x;
    const void* W = g_rp[5]; const int m = g_bf[5];
    const void* S = g_rp[6]; const int sbf = g_bf[6];
    size_t row = i >> 7;
    unsigned cb = ((unsigned)i & 127u) * 4u;
    float sc = ldf(S, sbf, row * 32 + (cb >> 4)) * 0.5f;
    float v[8];
    #pragma unroll
    for (int q = 0; q < 4; q++) {
        unsigned by = ldb(W, m, row * 512 + cb + q);
        v[2 * q]     = fp4v(by & 15u) * sc;
        v[2 * q + 1] = fp4v(by >> 4)  * sc;
    }
    uint4 o = make_uint4(pack_bf2(v[0], v[1]), pack_bf2(v[2], v[3]),
                         pack_bf2(v[4], v[5]), pack_bf2(v[6], v[7]));
    ((uint4*)g_wdn)[i] = o;
}

// ---------------- split x into hi/lo bf16 ----------------
__global__ void k_split_x() {
    size_t g = (size_t)blockIdx.x * 256 + threadIdx.x;
    const void* xp = g_rp[0]; const int xbf = g_bf[0];
    size_t b = g * 4;
    uint32_t hi[2], lo[2];
    #pragma unroll
    for (int q = 0; q < 2; q++) {
        float v0 = ldf(xp, xbf, b + 2 * q);
        float v1 = ldf(xp, xbf, b + 2 * q + 1);
        __nv_bfloat16 h0 = __float2bfloat16(v0), h1 = __float2bfloat16(v1);
        float r0 = v0 - __bfloat162float(h0), r1 = v1 - __bfloat162float(h1);
        hi[q] = (uint32_t)__bfloat16_as_ushort(h0) | ((uint32_t)__bfloat16_as_ushort(h1) << 16);
        lo[q] = (uint32_t)__bfloat16_as_ushort(__float2bfloat16(r0)) |
                ((uint32_t)__bfloat16_as_ushort(__float2bfloat16(r1)) << 16);
    }
    ((uint2*)g_xhi)[g] = make_uint2(hi[0], hi[1]);
    ((uint2*)g_xlo)[g] = make_uint2(lo[0], lo[1]);
}

// ---------------- routing ----------------
__global__ void k_route() {
    int s = blockIdx.x * 256 + threadIdx.x;
    if (s >= NSLOT) return;
    int e = ldid(g_rp[1], g_bf[1], s) & (NEXP - 1);
    int p = atomicAdd(&g_cnt[e], 1);
    g_slot[e * NSLOT + p] = s;
    g_wt[e * NSLOT + p]   = ldf(g_rp[2], g_bf[2], s);
}

// =====================================================================
// wmma bf16 grouped GEMMs, 2-stage cp.async pipeline.
// CTA tile 128x128, BK=64, 8 warps (4x2). hi/lo A accumulate together.
// Stage: sAhi|sAlo|sB, each 128x72 bf16 => 55296 B. Two stages.
// =====================================================================
extern __shared__ char dsm[];
#define LDA 72
#define LDS_ 132
#define STAGE_B 55296

// GEMM1: per (64-f tile, 128-slot tile, expert): gate|up, fused SwiGLU
__global__ void __launch_bounds__(256) k_mma1() {
    const int e = blockIdx.z, cnt = g_cnt[e];
    const int m0 = blockIdx.y * 128;
    if (m0 >= cnt) return;
    const int n0 = blockIdx.x * 64;

    float* S = (float*)dsm;
    __shared__ int sSlot[128], sTok[128];
    __shared__ float sWt[128];

    const int tid = threadIdx.x, wid = tid >> 5;
    if (tid < 128) {
        int m = m0 + tid;
        int sl = (m < cnt) ? g_slot[e * NSLOT + m] : g_slot[e * NSLOT];
        sSlot[tid] = sl; sTok[tid] = sl >> 2;
        sWt[tid] = (m < cnt) ? g_wt[e * NSLOT + m] : 0.f;
    }
    __syncthreads();

    // per-thread copy descriptors (4 chunks of 3x16B per stage)
    const uint32_t smBase = s2u(dsm);
    const __nv_bfloat16* BGU = g_wgu + (size_t)e * 2 * F_DIM * H_DIM;
    const __nv_bfloat16* gHi[4];
    const __nv_bfloat16* gLo[4];
    const __nv_bfloat16* gB[4];
    uint32_t sOff[4];
    #pragma unroll
    for (int q = 0; q < 4; q++) {
        int i = tid + q * 256;
        int r = i >> 3, c8 = i & 7;
        gHi[q] = g_xhi + (size_t)sTok[r] * H_DIM + c8 * 8;
        gLo[q] = g_xlo + (size_t)sTok[r] * H_DIM + c8 * 8;
        int rowW = (r < 64) ? (n0 + r) : (F_DIM + n0 + r - 64);
        gB[q]  = BGU + (size_t)rowW * H_DIM + c8 * 8;
        sOff[q] = (uint32_t)(r * LDA + c8 * 8) * 2u;
    }

    #define ISSUE1(kc) do { \
        uint32_t sb = smBase + (uint32_t)((kc) & 1) * STAGE_B; \
        int koff = (kc) * 64; \
        _Pragma("unroll") \
        for (int q = 0; q < 4; q++) { \
            cp16(sb + sOff[q],          gHi[q] + koff); \
            cp16(sb + 18432 + sOff[q],  gLo[q] + koff); \
            cp16(sb + 36864 + sOff[q],  gB[q]  + koff); \
        } \
        cp_commit(); \
    } while (0)

    const int wm = (wid & 3) * 32, wn = (wid >> 2) * 64;
    wmma::fragment<wmma::accumulator, 16, 16, 16, float> acc[2][4];
    #pragma unroll
    for (int i = 0; i < 2; i++)
        #pragma unroll
        for (int j = 0; j < 4; j++) wmma::fill_fragment(acc[i][j], 0.f);

    const int NK = H_DIM / 64;
    ISSUE1(0);
    for (int kc = 0; kc < NK; kc++) {
        if (kc + 1 < NK) { ISSUE1(kc + 1); cp_wait<1>(); }
        else             { cp_wait<0>(); }
        __syncthreads();
        const char* stg = dsm + (size_t)(kc & 1) * STAGE_B;
        const __nv_bfloat16* sAhi = (const __nv_bfloat16*)stg;
        const __nv_bfloat16* sAlo = (const __nv_bfloat16*)(stg + 18432);
        const __nv_bfloat16* sB   = (const __nv_bfloat16*)(stg + 36864);
        #pragma unroll
        for (int ks = 0; ks < 4; ks++) {
            wmma::fragment<wmma::matrix_b, 16, 16, 16, __nv_bfloat16, wmma::col_major> bf[4];
            #pragma unroll
            for (int nf = 0; nf < 4; nf++)
                wmma::load_matrix_sync(bf[nf], sB + (wn + nf * 16) * LDA + ks * 16, LDA);
            #pragma unroll
            for (int mf = 0; mf < 2; mf++) {
                wmma::fragment<wmma::matrix_a, 16, 16, 16, __nv_bfloat16, wmma::row_major> ah, al;
                wmma::load_matrix_sync(ah, sAhi + (wm + mf * 16) * LDA + ks * 16, LDA);
                wmma::load_matrix_sync(al, sAlo + (wm + mf * 16) * LDA + ks * 16, LDA);
                #pragma unroll
                for (int nf = 0; nf < 4; nf++) {
                    wmma::mma_sync(acc[mf][nf], ah, bf[nf], acc[mf][nf]);
                    wmma::mma_sync(acc[mf][nf], al, bf[nf], acc[mf][nf]);
                }
            }
        }
        __syncthreads();
    }
    #pragma unroll
    for (int mf = 0; mf < 2; mf++)
        #pragma unroll
        for (int nf = 0; nf < 4; nf++)
            wmma::store_matrix_sync(S + (wm + mf * 16) * LDS_ + wn + nf * 16,
                                    acc[mf][nf], LDS_, wmma::mem_row_major);
    __syncthreads();

    // SwiGLU epilogue: cols [0,64)=gate, [64,128)=up → act hi/lo
    {
        const int row = tid >> 1, j0 = (tid & 1) * 32;
        if (m0 + row < cnt) {
            const float wt = sWt[row];
            const size_t arow = (size_t)sSlot[row] * F_DIM + n0 + j0;
            #pragma unroll
            for (int q = 0; q < 4; q++) {
                uint32_t hw[4], lw[4];
                #pragma unroll
                for (int r2 = 0; r2 < 4; r2++) {
                    int j = j0 + q * 8 + r2 * 2;
                    float g0 = S[row * LDS_ + j],     u0 = S[row * LDS_ + 64 + j];
                    float g1 = S[row * LDS_ + j + 1], u1 = S[row * LDS_ + 65 + j];
                    float v0 = g0 * (1.f / (1.f + __expf(-g0))) * u0 * wt;
                    float v1 = g1 * (1.f / (1.f + __expf(-g1))) * u1 * wt;
                    __nv_bfloat16 h0 = __float2bfloat16(v0), h1 = __float2bfloat16(v1);
                    float r0 = v0 - __bfloat162float(h0), r1 = v1 - __bfloat162float(h1);
                    hw[r2] = (uint32_t)__bfloat16_as_ushort(h0) | ((uint32_t)__bfloat16_as_ushort(h1) << 16);
                    lw[r2] = (uint32_t)__bfloat16_as_ushort(__float2bfloat16(r0)) |
                             ((uint32_t)__bfloat16_as_ushort(__float2bfloat16(r1)) << 16);
                }
                ((uint4*)(g_ahi + arow))[q] = make_uint4(hw[0], hw[1], hw[2], hw[3]);
                ((uint4*)(g_alo + arow))[q] = make_uint4(lw[0], lw[1], lw[2], lw[3]);
            }
        }
    }
}

// GEMM2: per (128-h tile, 128-slot tile, expert): part = act @ Wd^T
__global__ void __launch_bounds__(256) k_mma2() {
    const int e = blockIdx.z, cnt = g_cnt[e];
    const int m0 = blockIdx.y * 128;
    if (m0 >= cnt) return;
    const int n0 = blockIdx.x * 128;

    float* S = (float*)dsm;
    __shared__ int sSlot[128];

    const int tid = threadIdx.x, wid = tid >> 5;
    if (tid < 128) {
        int m = m0 + tid;
        sSlot[tid] = (m < cnt) ? g_slot[e * NSLOT + m] : g_slot[e * NSLOT];
    }
    __syncthreads();

    const uint32_t smBase = s2u(dsm);
    const __nv_bfloat16* BW = g_wdn + (size_t)e * H_DIM * F_DIM;
    const __nv_bfloat16* gHi[4];
    const __nv_bfloat16* gLo[4];
    const __nv_bfloat16* gB[4];
    uint32_t sOff[4];
    #pragma unroll
    for (int q = 0; q < 4; q++) {
        int i = tid + q * 256;
        int r = i >> 3, c8 = i & 7;
        gHi[q] = g_ahi + (size_t)sSlot[r] * F_DIM + c8 * 8;
        gLo[q] = g_alo + (size_t)sSlot[r] * F_DIM + c8 * 8;
        gB[q]  = BW + (size_t)(n0 + r) * F_DIM + c8 * 8;
        sOff[q] = (uint32_t)(r * LDA + c8 * 8) * 2u;
    }

    #define ISSUE2(kc) do { \
        uint32_t sb = smBase + (uint32_t)((kc) & 1) * STAGE_B; \
        int koff = (kc) * 64; \
        _Pragma("unroll") \
        for (int q = 0; q < 4; q++) { \
            cp16(sb + sOff[q],          gHi[q] + koff); \
            cp16(sb + 18432 + sOff[q],  gLo[q] + koff); \
            cp16(sb + 36864 + sOff[q],  gB[q]  + koff); \
        } \
        cp_commit(); \
    } while (0)

    const int wm = (wid & 3) * 32, wn = (wid >> 2) * 64;
    wmma::fragment<wmma::accumulator, 16, 16, 16, float> acc[2][4];
    #pragma unroll
    for (int i = 0; i < 2; i++)
        #pragma unroll
        for (int j = 0; j < 4; j++) wmma::fill_fragment(acc[i][j], 0.f);

    const int NK = F_DIM / 64;
    ISSUE2(0);
    for (int kc = 0; kc < NK; kc++) {
        if (kc + 1 < NK) { ISSUE2(kc + 1); cp_wait<1>(); }
        else             { cp_wait<0>(); }
        __syncthreads();
        const char* stg = dsm + (size_t)(kc & 1) * STAGE_B;
        const __nv_bfloat16* sAhi = (const __nv_bfloat16*)stg;
        const __nv_bfloat16* sAlo = (const __nv_bfloat16*)(stg + 18432);
        const __nv_bfloat16* sB   = (const __nv_bfloat16*)(stg + 36864);
        #pragma unroll
        for (int ks = 0; ks < 4; ks++) {
            wmma::fragment<wmma::matrix_b, 16, 16, 16, __nv_bfloat16, wmma::col_major> bf[4];
            #pragma unroll
            for (int nf = 0; nf < 4; nf++)
                wmma::load_matrix_sync(bf[nf], sB + (wn + nf * 16) * LDA + ks * 16, LDA);
            #pragma unroll
            for (int mf = 0; mf < 2; mf++) {
                wmma::fragment<wmma::matrix_a, 16, 16, 16, __nv_bfloat16, wmma::row_major> ah, al;
                wmma::load_matrix_sync(ah, sAhi + (wm + mf * 16) * LDA + ks * 16, LDA);
                wmma::load_matrix_sync(al, sAlo + (wm + mf * 16) * LDA + ks * 16, LDA);
                #pragma unroll
                for (int nf = 0; nf < 4; nf++) {
                    wmma::mma_sync(acc[mf][nf], ah, bf[nf], acc[mf][nf]);
                    wmma::mma_sync(acc[mf][nf], al, bf[nf], acc[mf][nf]);
                }
            }
        }
        __syncthreads();
    }
    #pragma unroll
    for (int mf = 0; mf < 2; mf++)
        #pragma unroll
        for (int nf = 0; nf < 4; nf++)
            wmma::store_matrix_sync(S + (wm + mf * 16) * LDS_ + wn + nf * 16,
                                    acc[mf][nf], LDS_, wmma::mem_row_major);
    __syncthreads();

    {
        const int row = tid >> 1, h0 = (tid & 1) * 64;
        if (m0 + row < cnt) {
            const size_t prow = (size_t)sSlot[row] * H_DIM + n0 + h0;
            #pragma unroll
            for (int q = 0; q < 16; q++) {
                float4 o = make_float4(S[row * LDS_ + h0 + q * 4],
                                       S[row * LDS_ + h0 + q * 4 + 1],
                                       S[row * LDS_ + h0 + q * 4 + 2],
                                       S[row * LDS_ + h0 + q * 4 + 3]);
                ((float4*)(g_part + prow))[q] = o;
            }
        }
    }
}

// deterministic 4-way reduce; dtype-flexible output
__global__ void k_reduce(void* __restrict__ outv) {
    int idx = blockIdx.x * 256 + threadIdx.x;
    int t = idx / (H_DIM / 4);
    int c = idx % (H_DIM / 4);
    const float4* p = (const float4*)g_part;
    float4 a = p[(size_t)(t * 4 + 0) * (H_DIM / 4) + c];
    float4 b = p[(size_t)(t * 4 + 1) * (H_DIM / 4) + c];
    float4 d = p[(size_t)(t * 4 + 2) * (H_DIM / 4) + c];
    float4 e = p[(size_t)(t * 4 + 3) * (H_DIM / 4) + c];
    float s0 = a.x + b.x + d.x + e.x, s1 = a.y + b.y + d.y + e.y;
    float s2 = a.z + b.z + d.z + e.z, s3 = a.w + b.w + d.w + e.w;
    if (g_bf[7]) {
        __nv_bfloat16* ob = (__nv_bfloat16*)outv;
        size_t base = (size_t)t * H_DIM + c * 4;
        ob[base + 0] = __float2bfloat16(s0);
        ob[base + 1] = __float2bfloat16(s1);
        ob[base + 2] = __float2bfloat16(s2);
        ob[base + 3] = __float2bfloat16(s3);
    } else {
        ((float4*)outv)[(size_t)t * (H_DIM / 4) + c] = make_float4(s0, s1, s2, s3);
    }
}

extern "C" void kernel_launch(void* const* d_in, const int* in_sizes, int n_in,
                              void* d_out, int out_size) {
    InPtrs in;
    int n = (n_in < 8) ? n_in : 8;
    for (int i = 0; i < 8; i++) {
        in.p[i]  = (i < n) ? d_in[i] : nullptr;
        in.sz[i] = (i < n) ? (long long)in_sizes[i] : 0;
    }
    in.n = n;

    const int DSMEM = 2 * STAGE_B;   // 110592 (covers 67584 epilogue buffer)
    cudaFuncSetAttribute(k_mma1, cudaFuncAttributeMaxDynamicSharedMemorySize, DSMEM);
    cudaFuncSetAttribute(k_mma2, cudaFuncAttributeMaxDynamicSharedMemorySize, DSMEM);

    k_resolve<<<1, 256>>>(in);
    k_deq_gu<<<(NEXP * 2 * F_DIM * (H_DIM / 2) / 4) / 256, 256>>>();
    k_deq_dn<<<(NEXP * H_DIM * (F_DIM / 2) / 4) / 256, 256>>>();
    k_split_x<<<(T_TOK * H_DIM / 4) / 256, 256>>>();
    k_route<<<NSLOT / 256, 256>>>();
    k_mma1<<<dim3(F_DIM / 64, NSLOT / 128, NEXP), 256, DSMEM>>>();
    k_mma2<<<dim3(H_DIM / 128, NSLOT / 128, NEXP), 256, DSMEM>>>();
    k_reduce<<<(T_TOK * H_DIM / 4) / 256, 256>>>(d_out);
}

// round 16
// speedup vs baseline: 1.0544x; 1.0544x over previous
#include <cuda_runtime.h>
#include <cuda_bf16.h>
#include <mma.h>
#include <cstdint>

using namespace nvcuda;

#define T_TOK 2048
#define H_DIM 2048
#define F_DIM 1024
#define NEXP  16
#define TOPK  4
#define NSLOT (T_TOK * TOPK)   // 8192

// ---------------- device scratch ----------------
__device__ int   g_cnt[NEXP];
__device__ int   g_slot[NEXP * NSLOT];
__device__ float g_wt[NEXP * NSLOT];
__device__ float g_part[(size_t)NSLOT * H_DIM];                    // 64 MB
__device__ __nv_bfloat16 g_wgu[(size_t)NEXP * 2 * F_DIM * H_DIM];  // 128 MB dequant
__device__ __nv_bfloat16 g_wdn[(size_t)NEXP * H_DIM * F_DIM];      // 64 MB dequant
__device__ __nv_bfloat16 g_xhi[(size_t)T_TOK * H_DIM];             // 8 MB
__device__ __nv_bfloat16 g_xlo[(size_t)T_TOK * H_DIM];             // 8 MB
__device__ __nv_bfloat16 g_ahi[(size_t)NSLOT * F_DIM];             // 16 MB
__device__ __nv_bfloat16 g_alo[(size_t)NSLOT * F_DIM];             // 16 MB

// resolved pointers: 0=x 1=ids 2=wts 3=guw 4=gus 5=dwn 6=dsc
__device__ const void* g_rp[7];
__device__ int g_bf[8];

struct InPtrs { const void* p[8]; long long sz[8]; int n; };

__device__ __forceinline__ float bfh(unsigned h) { return __uint_as_float(h << 16); }

// ---------------- content+dtype based input resolution (proven R8) ----------------
__global__ void k_resolve(InPtrs in) {
    __shared__ int cls[8], bff[8];
    __shared__ long long ssz[8];
    int w = threadIdx.x >> 5, lane = threadIdx.x & 31;
    if (w < 8 && lane == 0) { cls[w] = -1; bff[w] = 0; ssz[w] = 0; }
    __syncthreads();
    if (w < in.n && w < 8) {
        const unsigned* u = (const unsigned*)in.p[w];
        bool lt16 = true, i64ids = true, i64b = true, u32b = true;
        bool fint16 = true, fint256 = true;
        bool f32unit = true, f32mant0 = true, f32small = true;
        bool bfunit = true, bfpow2 = true, bfsmall = true;
        bool neg32 = false, pos32 = false, negB = false, posB = false;
        #pragma unroll
        for (int j = 0; j < 4; j++) {
            int idx = lane + 32 * j;
            unsigned v = u[idx];
            lt16   &= (v < 16u);
            i64ids &= (idx & 1) ? (v == 0u) : (v < 16u);
            i64b   &= (idx & 1) ? (v == 0u) : (v < 256u);
            u32b   &= (v < 256u);
            float f = __uint_as_float(v);
            unsigned ex = (v >> 23) & 255u;
            bool fin = (ex != 255u);
            bool isint = fin && f >= 0.f && f == floorf(f);
            fint16  &= (isint && f < 16.f);
            fint256 &= (isint && f < 256.f);
            f32unit  &= (fin && f > 0.f && f < 1.f);
            f32mant0 &= ((v & 0x7FFFFFu) == 0u);
            f32small &= (fin && fabsf(f) < 100.f);
            neg32 |= (f < 0.f); pos32 |= (f > 0.f);
            unsigned hs[2] = { v >> 16, v & 0xFFFFu };
            #pragma unroll
            for (int q = 0; q < 2; q++) {
                unsigned h = hs[q];
                float fb = bfh(h);
                bool finB = (((h >> 7) & 255u) != 255u);
                bfunit  &= (finB && fb > 0.f && fb < 1.f);
                bfpow2  &= (finB && fb > 0.f && fb < 1.f && ((h & 127u) == 0u));
                bfsmall &= (finB && fabsf(fb) < 100.f);
                negB |= (fb < 0.f); posB |= (fb > 0.f);
            }
        }
        unsigned full = ~0u;
        lt16 = __all_sync(full, lt16);       i64ids = __all_sync(full, i64ids);
        i64b = __all_sync(full, i64b);       u32b = __all_sync(full, u32b);
        fint16 = __all_sync(full, fint16);   fint256 = __all_sync(full, fint256);
        f32unit = __all_sync(full, f32unit); f32mant0 = __all_sync(full, f32mant0);
        f32small = __all_sync(full, f32small);
        bfunit = __all_sync(full, bfunit);   bfpow2 = __all_sync(full, bfpow2);
        bfsmall = __all_sync(full, bfsmall);
        neg32 = __any_sync(full, neg32);     pos32 = __any_sync(full, pos32);
        negB = __any_sync(full, negB);       posB = __any_sync(full, posB);
        if (lane == 0) {
            int c, bf = 0;
            if (lt16)                         { c = 0; }
            else if (i64ids)                  { c = 0; bf = 2; }
            else if (fint16)                  { c = 0; bf = 3; }
            else if (i64b)                    { c = 4; bf = 5; }
            else if (u32b)                    { c = 4; bf = 3; }
            else if (fint256)                 { c = 4; bf = 4; }
            else if (f32unit && f32mant0)     { c = 2; }
            else if (bfunit && bfpow2)        { c = 2; bf = 1; }
            else if (f32unit)                 { c = 1; }
            else if (bfunit)                  { c = 1; bf = 1; }
            else if (f32small && neg32 && pos32) { c = 3; }
            else if (bfsmall && negB && posB)    { c = 3; bf = 1; }
            else                              { c = 4; bf = 0; }
            cls[w] = c; bff[w] = bf; ssz[w] = in.sz[w];
        }
    }
    __syncthreads();
    if (threadIdx.x == 0) {
        int ix = -1, ii = -1, iw = -1, s1 = -1, s2 = -1, p1 = -1, p2 = -1;
        for (int i = 0; i < in.n && i < 8; i++) {
            switch (cls[i]) {
                case 0: ii = i; break;
                case 1: iw = i; break;
                case 2: if (s1 < 0) s1 = i; else s2 = i; break;
                case 3: ix = i; break;
                case 4: if (p1 < 0) p1 = i; else p2 = i; break;
                default: break;
            }
        }
        if (ix >= 0 && ii >= 0 && iw >= 0 && s2 >= 0 && p2 >= 0) {
            int gus_i = s1, dsc_i = s2;
            if (ssz[s2] > ssz[s1]) { gus_i = s2; dsc_i = s1; }
            int guw_i = p1, dwn_i = p2;
            if (ssz[p2] > ssz[p1]) { guw_i = p2; dwn_i = p1; }
            g_rp[0] = in.p[ix];    g_bf[0] = bff[ix];
            g_rp[1] = in.p[ii];    g_bf[1] = bff[ii];
            g_rp[2] = in.p[iw];    g_bf[2] = bff[iw];
            g_rp[3] = in.p[guw_i]; g_bf[3] = bff[guw_i];
            g_rp[4] = in.p[gus_i]; g_bf[4] = bff[gus_i];
            g_rp[5] = in.p[dwn_i]; g_bf[5] = bff[dwn_i];
            g_rp[6] = in.p[dsc_i]; g_bf[6] = bff[dsc_i];
            g_bf[7] = bff[ix];
        } else {
            g_rp[0] = in.p[0]; g_rp[2] = in.p[1]; g_rp[1] = in.p[2];
            g_rp[3] = in.p[3]; g_rp[4] = in.p[4]; g_rp[5] = in.p[5]; g_rp[6] = in.p[6];
            for (int i = 0; i < 8; i++) g_bf[i] = 0;
        }
        for (int e = 0; e < NEXP; e++) g_cnt[e] = 0;
    }
}

// ---------------- helpers ----------------
__device__ __forceinline__ float ldf(const void* p, int bf, size_t i) {
    return bf ? __bfloat162float(((const __nv_bfloat16*)p)[i]) : ((const float*)p)[i];
}
__device__ __forceinline__ int ldid(const void* p, int flag, int i) {
    if (flag == 2) return (int)((const long long*)p)[i];
    if (flag == 3) return (int)((const float*)p)[i];
    return ((const int*)p)[i];
}
__device__ __forceinline__ unsigned ldb(const void* p, int m, size_t i) {
    switch (m) {
        case 3:  return ((const unsigned*)p)[i] & 255u;
        case 4:  return (unsigned)((const float*)p)[i] & 255u;
        case 5:  return (unsigned)(((const unsigned long long*)p)[i] & 255ull);
        default: return ((const uint8_t*)p)[i];
    }
}
__device__ __forceinline__ float fp4v(unsigned n) {
    float m = (float)((0xC8643210u >> ((n & 7u) * 4)) & 15u);
    return (n & 8u) ? -m : m;
}
__device__ __forceinline__ uint32_t pack_bf2(float a, float b) {
    unsigned short ha = __bfloat16_as_ushort(__float2bfloat16(a));
    unsigned short hb = __bfloat16_as_ushort(__float2bfloat16(b));
    return (uint32_t)ha | ((uint32_t)hb << 16);
}
__device__ __forceinline__ uint32_t s2u(const void* p) {
    uint32_t a;
    asm("{ .reg .u64 t; cvta.to.shared.u64 t, %1; cvt.u32.u64 %0, t; }" : "=r"(a) : "l"(p));
    return a;
}
__device__ __forceinline__ void cp16(uint32_t saddr, const void* gaddr) {
    asm volatile("cp.async.cg.shared.global [%0], [%1], 16;" :: "r"(saddr), "l"(gaddr) : "memory");
}
__device__ __forceinline__ void cp_commit() {
    asm volatile("cp.async.commit_group;" ::: "memory");
}
template <int N>
__device__ __forceinline__ void cp_wait() {
    asm volatile("cp.async.wait_group %0;" :: "n"(N) : "memory");
}

// ---------------- one-time weight dequant to bf16 ----------------
__global__ void k_deq_gu() {
    size_t i = (size_t)blockIdx.x * 256 + threadIdx.x;
    const void* W = g_rp[3]; const int m = g_bf[3];
    const void* S = g_rp[4]; const int sbf = g_bf[4];
    size_t row = i >> 8;
    unsigned cb = ((unsigned)i & 255u) * 4u;
    float sc = ldf(S, sbf, row * 64 + (cb >> 4)) * 0.5f;
    float v[8];
    #pragma unroll
    for (int q = 0; q < 4; q++) {
        unsigned by = ldb(W, m, row * 1024 + cb + q);
        v[2 * q]     = fp4v(by & 15u) * sc;
        v[2 * q + 1] = fp4v(by >> 4)  * sc;
    }
    uint4 o = make_uint4(pack_bf2(v[0], v[1]), pack_bf2(v[2], v[3]),
                         pack_bf2(v[4], v[5]), pack_bf2(v[6], v[7]));
    ((uint4*)g_wgu)[i] = o;
}
__global__ void k_deq_dn() {
    size_t i = (size_t)blockIdx.x * 256 + threadIdx.x;
    const void* W = g_rp[5]; const int m = g_bf[5];
    const void* S = g_rp[6]; const int sbf = g_bf[6];
    size_t row = i >> 7;
    unsigned cb = ((unsigned)i & 127u) * 4u;
    float sc = ldf(S, sbf, row * 32 + (cb >> 4)) * 0.5f;
    float v[8];
    #pragma unroll
    for (int q = 0; q < 4; q++) {
        unsigned by = ldb(W, m, row * 512 + cb + q);
        v[2 * q]     = fp4v(by & 15u) * sc;
        v[2 * q + 1] = fp4v(by >> 4)  * sc;
    }
    uint4 o = make_uint4(pack_bf2(v[0], v[1]), pack_bf2(v[2], v[3]),
                         pack_bf2(v[4], v[5]), pack_bf2(v[6], v[7]));
    ((uint4*)g_wdn)[i] = o;
}

// ---------------- split x into hi/lo bf16 ----------------
__global__ void k_split_x() {
    size_t g = (size_t)blockIdx.x * 256 + threadIdx.x;
    const void* xp = g_rp[0]; const int xbf = g_bf[0];
    size_t b = g * 4;
    uint32_t hi[2], lo[2];
    #pragma unroll
    for (int q = 0; q < 2; q++) {
        float v0 = ldf(xp, xbf, b + 2 * q);
        float v1 = ldf(xp, xbf, b + 2 * q + 1);
        __nv_bfloat16 h0 = __float2bfloat16(v0), h1 = __float2bfloat16(v1);
        float r0 = v0 - __bfloat162float(h0), r1 = v1 - __bfloat162float(h1);
        hi[q] = (uint32_t)__bfloat16_as_ushort(h0) | ((uint32_t)__bfloat16_as_ushort(h1) << 16);
        lo[q] = (uint32_t)__bfloat16_as_ushort(__float2bfloat16(r0)) |
                ((uint32_t)__bfloat16_as_ushort(__float2bfloat16(r1)) << 16);
    }
    ((uint2*)g_xhi)[g] = make_uint2(hi[0], hi[1]);
    ((uint2*)g_xlo)[g] = make_uint2(lo[0], lo[1]);
}

// ---------------- routing ----------------
__global__ void k_route() {
    int s = blockIdx.x * 256 + threadIdx.x;
    if (s >= NSLOT) return;
    int e = ldid(g_rp[1], g_bf[1], s) & (NEXP - 1);
    int p = atomicAdd(&g_cnt[e], 1);
    g_slot[e * NSLOT + p] = s;
    g_wt[e * NSLOT + p]   = ldf(g_rp[2], g_bf[2], s);
}

// =====================================================================
// wmma bf16 grouped GEMMs, 3-stage cp.async pipeline, BK=32.
// CTA tile 128x128, 8 warps (4x2). hi/lo A accumulate together.
// Stage: sAhi|sAlo|sB, each 128x40 bf16 (data 128x32) = 10240 B -> 30720/stage.
// 3 stages = 92160 B dsmem => 2 CTAs/SM.
// =====================================================================
extern __shared__ char dsm[];
#define LDA 40
#define LDS_ 132
#define STAGE_B 30720
#define ARR_B 10240

// GEMM1: per (64-f tile, 128-slot tile, expert): gate|up, fused SwiGLU
__global__ void __launch_bounds__(256, 2) k_mma1() {
    const int e = blockIdx.z, cnt = g_cnt[e];
    const int m0 = blockIdx.y * 128;
    if (m0 >= cnt) return;
    const int n0 = blockIdx.x * 64;

    float* S = (float*)dsm;
    __shared__ int sSlot[128], sTok[128];
    __shared__ float sWt[128];

    const int tid = threadIdx.x, wid = tid >> 5;
    if (tid < 128) {
        int m = m0 + tid;
        int sl = (m < cnt) ? g_slot[e * NSLOT + m] : g_slot[e * NSLOT];
        sSlot[tid] = sl; sTok[tid] = sl >> 2;
        sWt[tid] = (m < cnt) ? g_wt[e * NSLOT + m] : 0.f;
    }
    __syncthreads();

    // per-thread copy descriptors: 2 chunks of 16B per array per stage
    const uint32_t smBase = s2u(dsm);
    const __nv_bfloat16* BGU = g_wgu + (size_t)e * 2 * F_DIM * H_DIM;
    const __nv_bfloat16* gHi[2];
    const __nv_bfloat16* gLo[2];
    const __nv_bfloat16* gB[2];
    uint32_t sOff[2];
    #pragma unroll
    for (int q = 0; q < 2; q++) {
        int i = tid + q * 256;
        int r = i >> 2, c = (i & 3) * 8;       // 4 chunks x 8 bf16 per row of 32
        gHi[q] = g_xhi + (size_t)sTok[r] * H_DIM + c;
        gLo[q] = g_xlo + (size_t)sTok[r] * H_DIM + c;
        int rowW = (r < 64) ? (n0 + r) : (F_DIM + n0 + r - 64);
        gB[q]  = BGU + (size_t)rowW * H_DIM + c;
        sOff[q] = (uint32_t)(r * LDA + c) * 2u;
    }

    #define ISSUE1(kc) do { \
        uint32_t sb = smBase + (uint32_t)((kc) % 3) * STAGE_B; \
        int koff = (kc) * 32; \
        _Pragma("unroll") \
        for (int q = 0; q < 2; q++) { \
            cp16(sb + sOff[q],              gHi[q] + koff); \
            cp16(sb + ARR_B + sOff[q],      gLo[q] + koff); \
            cp16(sb + 2 * ARR_B + sOff[q],  gB[q]  + koff); \
        } \
        cp_commit(); \
    } while (0)

    const int wm = (wid & 3) * 32, wn = (wid >> 2) * 64;
    wmma::fragment<wmma::accumulator, 16, 16, 16, float> acc[2][4];
    #pragma unroll
    for (int i = 0; i < 2; i++)
        #pragma unroll
        for (int j = 0; j < 4; j++) wmma::fill_fragment(acc[i][j], 0.f);

    const int NK = H_DIM / 32;
    ISSUE1(0); ISSUE1(1);
    for (int kc = 0; kc < NK; kc++) {
        if (kc + 2 < NK)      { ISSUE1(kc + 2); cp_wait<2>(); }
        else if (kc + 1 < NK) { cp_wait<1>(); }
        else                  { cp_wait<0>(); }
        __syncthreads();
        const char* stg = dsm + (size_t)(kc % 3) * STAGE_B;
        const __nv_bfloat16* sAhi = (const __nv_bfloat16*)stg;
        const __nv_bfloat16* sAlo = (const __nv_bfloat16*)(stg + ARR_B);
        const __nv_bfloat16* sB   = (const __nv_bfloat16*)(stg + 2 * ARR_B);
        #pragma unroll
        for (int ks = 0; ks < 2; ks++) {
            wmma::fragment<wmma::matrix_b, 16, 16, 16, __nv_bfloat16, wmma::col_major> bf[4];
            #pragma unroll
            for (int nf = 0; nf < 4; nf++)
                wmma::load_matrix_sync(bf[nf], sB + (wn + nf * 16) * LDA + ks * 16, LDA);
            #pragma unroll
            for (int mf = 0; mf < 2; mf++) {
                wmma::fragment<wmma::matrix_a, 16, 16, 16, __nv_bfloat16, wmma::row_major> ah, al;
                wmma::load_matrix_sync(ah, sAhi + (wm + mf * 16) * LDA + ks * 16, LDA);
                wmma::load_matrix_sync(al, sAlo + (wm + mf * 16) * LDA + ks * 16, LDA);
                #pragma unroll
                for (int nf = 0; nf < 4; nf++) {
                    wmma::mma_sync(acc[mf][nf], ah, bf[nf], acc[mf][nf]);
                    wmma::mma_sync(acc[mf][nf], al, bf[nf], acc[mf][nf]);
                }
            }
        }
        __syncthreads();
    }
    #pragma unroll
    for (int mf = 0; mf < 2; mf++)
        #pragma unroll
        for (int nf = 0; nf < 4; nf++)
            wmma::store_matrix_sync(S + (wm + mf * 16) * LDS_ + wn + nf * 16,
                                    acc[mf][nf], LDS_, wmma::mem_row_major);
    __syncthreads();

    // SwiGLU epilogue: cols [0,64)=gate, [64,128)=up → act hi/lo
    {
        const int row = tid >> 1, j0 = (tid & 1) * 32;
        if (m0 + row < cnt) {
            const float wt = sWt[row];
            const size_t arow = (size_t)sSlot[row] * F_DIM + n0 + j0;
            #pragma unroll
            for (int q = 0; q < 4; q++) {
                uint32_t hw[4], lw[4];
                #pragma unroll
                for (int r2 = 0; r2 < 4; r2++) {
                    int j = j0 + q * 8 + r2 * 2;
                    float g0 = S[row * LDS_ + j],     u0 = S[row * LDS_ + 64 + j];
                    float g1 = S[row * LDS_ + j + 1], u1 = S[row * LDS_ + 65 + j];
                    float v0 = g0 * (1.f / (1.f + __expf(-g0))) * u0 * wt;
                    float v1 = g1 * (1.f / (1.f + __expf(-g1))) * u1 * wt;
                    __nv_bfloat16 h0 = __float2bfloat16(v0), h1 = __float2bfloat16(v1);
                    float r0 = v0 - __bfloat162float(h0), r1 = v1 - __bfloat162float(h1);
                    hw[r2] = (uint32_t)__bfloat16_as_ushort(h0) | ((uint32_t)__bfloat16_as_ushort(h1) << 16);
                    lw[r2] = (uint32_t)__bfloat16_as_ushort(__float2bfloat16(r0)) |
                             ((uint32_t)__bfloat16_as_ushort(__float2bfloat16(r1)) << 16);
                }
                ((uint4*)(g_ahi + arow))[q] = make_uint4(hw[0], hw[1], hw[2], hw[3]);
                ((uint4*)(g_alo + arow))[q] = make_uint4(lw[0], lw[1], lw[2], lw[3]);
            }
        }
    }
}

// GEMM2: per (128-h tile, 128-slot tile, expert): part = act @ Wd^T
__global__ void __launch_bounds__(256, 2) k_mma2() {
    const int e = blockIdx.z, cnt = g_cnt[e];
    const int m0 = blockIdx.y * 128;
    if (m0 >= cnt) return;
    const int n0 = blockIdx.x * 128;

    float* S = (float*)dsm;
    __shared__ int sSlot[128];

    const int tid = threadIdx.x, wid = tid >> 5;
    if (tid < 128) {
        int m = m0 + tid;
        sSlot[tid] = (m < cnt) ? g_slot[e * NSLOT + m] : g_slot[e * NSLOT];
    }
    __syncthreads();

    const uint32_t smBase = s2u(dsm);
    const __nv_bfloat16* BW = g_wdn + (size_t)e * H_DIM * F_DIM;
    const __nv_bfloat16* gHi[2];
    const __nv_bfloat16* gLo[2];
    const __nv_bfloat16* gB[2];
    uint32_t sOff[2];
    #pragma unroll
    for (int q = 0; q < 2; q++) {
        int i = tid + q * 256;
        int r = i >> 2, c = (i & 3) * 8;
        gHi[q] = g_ahi + (size_t)sSlot[r] * F_DIM + c;
        gLo[q] = g_alo + (size_t)sSlot[r] * F_DIM + c;
        gB[q]  = BW + (size_t)(n0 + r) * F_DIM + c;
        sOff[q] = (uint32_t)(r * LDA + c) * 2u;
    }

    #define ISSUE2(kc) do { \
        uint32_t sb = smBase + (uint32_t)((kc) % 3) * STAGE_B; \
        int koff = (kc) * 32; \
        _Pragma("unroll") \
        for (int q = 0; q < 2; q++) { \
            cp16(sb + sOff[q],              gHi[q] + koff); \
            cp16(sb + ARR_B + sOff[q],      gLo[q] + koff); \
            cp16(sb + 2 * ARR_B + sOff[q],  gB[q]  + koff); \
        } \
        cp_commit(); \
    } while (0)

    const int wm = (wid & 3) * 32, wn = (wid >> 2) * 64;
    wmma::fragment<wmma::accumulator, 16, 16, 16, float> acc[2][4];
    #pragma unroll
    for (int i = 0; i < 2; i++)
        #pragma unroll
        for (int j = 0; j < 4; j++) wmma::fill_fragment(acc[i][j], 0.f);

    const int NK = F_DIM / 32;
    ISSUE2(0); ISSUE2(1);
    for (int kc = 0; kc < NK; kc++) {
        if (kc + 2 < NK)      { ISSUE2(kc + 2); cp_wait<2>(); }
        else if (kc + 1 < NK) { cp_wait<1>(); }
        else                  { cp_wait<0>(); }
        __syncthreads();
        const char* stg = dsm + (size_t)(kc % 3) * STAGE_B;
        const __nv_bfloat16* sAhi = (const __nv_bfloat16*)stg;
        const __nv_bfloat16* sAlo = (const __nv_bfloat16*)(stg + ARR_B);
        const __nv_bfloat16* sB   = (const __nv_bfloat16*)(stg + 2 * ARR_B);
        #pragma unroll
        for (int ks = 0; ks < 2; ks++) {
            wmma::fragment<wmma::matrix_b, 16, 16, 16, __nv_bfloat16, wmma::col_major> bf[4];
            #pragma unroll
            for (int nf = 0; nf < 4; nf++)
                wmma::load_matrix_sync(bf[nf], sB + (wn + nf * 16) * LDA + ks * 16, LDA);
            #pragma unroll
            for (int mf = 0; mf < 2; mf++) {
                wmma::fragment<wmma::matrix_a, 16, 16, 16, __nv_bfloat16, wmma::row_major> ah, al;
                wmma::load_matrix_sync(ah, sAhi + (wm + mf * 16) * LDA + ks * 16, LDA);
                wmma::load_matrix_sync(al, sAlo + (wm + mf * 16) * LDA + ks * 16, LDA);
                #pragma unroll
                for (int nf = 0; nf < 4; nf++) {
                    wmma::mma_sync(acc[mf][nf], ah, bf[nf], acc[mf][nf]);
                    wmma::mma_sync(acc[mf][nf], al, bf[nf], acc[mf][nf]);
                }
            }
        }
        __syncthreads();
    }
    #pragma unroll
    for (int mf = 0; mf < 2; mf++)
        #pragma unroll
        for (int nf = 0; nf < 4; nf++)
            wmma::store_matrix_sync(S + (wm + mf * 16) * LDS_ + wn + nf * 16,
                                    acc[mf][nf], LDS_, wmma::mem_row_major);
    __syncthreads();

    {
        const int row = tid >> 1, h0 = (tid & 1) * 64;
        if (m0 + row < cnt) {
            const size_t prow = (size_t)sSlot[row] * H_DIM + n0 + h0;
            #pragma unroll
            for (int q = 0; q < 16; q++) {
                float4 o = make_float4(S[row * LDS_ + h0 + q * 4],
                                       S[row * LDS_ + h0 + q * 4 + 1],
                                       S[row * LDS_ + h0 + q * 4 + 2],
                                       S[row * LDS_ + h0 + q * 4 + 3]);
                ((float4*)(g_part + prow))[q] = o;
            }
        }
    }
}

// deterministic 4-way reduce; dtype-flexible output
__global__ void k_reduce(void* __restrict__ outv) {
    int idx = blockIdx.x * 256 + threadIdx.x;
    int t = idx / (H_DIM / 4);
    int c = idx % (H_DIM / 4);
    const float4* p = (const float4*)g_part;
    float4 a = p[(size_t)(t * 4 + 0) * (H_DIM / 4) + c];
    float4 b = p[(size_t)(t * 4 + 1) * (H_DIM / 4) + c];
    float4 d = p[(size_t)(t * 4 + 2) * (H_DIM / 4) + c];
    float4 e = p[(size_t)(t * 4 + 3) * (H_DIM / 4) + c];
    float s0 = a.x + b.x + d.x + e.x, s1 = a.y + b.y + d.y + e.y;
    float s2 = a.z + b.z + d.z + e.z, s3 = a.w + b.w + d.w + e.w;
    if (g_bf[7]) {
        __nv_bfloat16* ob = (__nv_bfloat16*)outv;
        size_t base = (size_t)t * H_DIM + c * 4;
        ob[base + 0] = __float2bfloat16(s0);
        ob[base + 1] = __float2bfloat16(s1);
        ob[base + 2] = __float2bfloat16(s2);
        ob[base + 3] = __float2bfloat16(s3);
    } else {
        ((float4*)outv)[(size_t)t * (H_DIM / 4) + c] = make_float4(s0, s1, s2, s3);
    }
}

extern "C" void kernel_launch(void* const* d_in, const int* in_sizes, int n_in,
                              void* d_out, int out_size) {
    InPtrs in;
    int n = (n_in < 8) ? n_in : 8;
    for (int i = 0; i < 8; i++) {
        in.p[i]  = (i < n) ? d_in[i] : nullptr;
        in.sz[i] = (i < n) ? (long long)in_sizes[i] : 0;
    }
    in.n = n;

    const int DSMEM = 3 * STAGE_B;   // 92160 (covers 67584 epilogue buffer)
    cudaFuncSetAttribute(k_mma1, cudaFuncAttributeMaxDynamicSharedMemorySize, DSMEM);
    cudaFuncSetAttribute(k_mma2, cudaFuncAttributeMaxDynamicSharedMemorySize, DSMEM);

    k_resolve<<<1, 256>>>(in);
    k_deq_gu<<<(NEXP * 2 * F_DIM * (H_DIM / 2) / 4) / 256, 256>>>();
    k_deq_dn<<<(NEXP * H_DIM * (F_DIM / 2) / 4) / 256, 256>>>();
    k_split_x<<<(T_TOK * H_DIM / 4) / 256, 256>>>();
    k_route<<<NSLOT / 256, 256>>>();
    k_mma1<<<dim3(F_DIM / 64, NSLOT / 128, NEXP), 256, DSMEM>>>();
    k_mma2<<<dim3(H_DIM / 128, NSLOT / 128, NEXP), 256, DSMEM>>>();
    k_reduce<<<(T_TOK * H_DIM / 4) / 256, 256>>>(d_out);
}

// round 17
// speedup vs baseline: 1.2061x; 1.1439x over previous
#include <cuda_runtime.h>
#include <cuda_bf16.h>
#include <cuda_fp16.h>
#include <mma.h>
#include <cstdint>

using namespace nvcuda;

#define T_TOK 2048
#define H_DIM 2048
#define F_DIM 1024
#define NEXP  16
#define TOPK  4
#define NSLOT (T_TOK * TOPK)   // 8192

// ---------------- device scratch ----------------
__device__ int   g_cnt[NEXP];
__device__ int   g_slot[NEXP * NSLOT];
__device__ float g_wt[NEXP * NSLOT];
__device__ float g_part[(size_t)NSLOT * H_DIM];              // 64 MB
__device__ __half g_wgu[(size_t)NEXP * 2 * F_DIM * H_DIM];   // 128 MB dequant fp16 (exact)
__device__ __half g_wdn[(size_t)NEXP * H_DIM * F_DIM];       // 64 MB dequant fp16 (exact)
__device__ __half g_x[(size_t)T_TOK * H_DIM];                // 8 MB
__device__ __half g_act[(size_t)NSLOT * F_DIM];              // 16 MB

// resolved pointers: 0=x 1=ids 2=wts 3=guw 4=gus 5=dwn 6=dsc
__device__ const void* g_rp[7];
__device__ int g_bf[8];

struct InPtrs { const void* p[8]; long long sz[8]; int n; };

__device__ __forceinline__ float bfh(unsigned h) { return __uint_as_float(h << 16); }

// ---------------- content+dtype based input resolution (proven R8) ----------------
__global__ void k_resolve(InPtrs in) {
    __shared__ int cls[8], bff[8];
    __shared__ long long ssz[8];
    int w = threadIdx.x >> 5, lane = threadIdx.x & 31;
    if (w < 8 && lane == 0) { cls[w] = -1; bff[w] = 0; ssz[w] = 0; }
    __syncthreads();
    if (w < in.n && w < 8) {
        const unsigned* u = (const unsigned*)in.p[w];
        bool lt16 = true, i64ids = true, i64b = true, u32b = true;
        bool fint16 = true, fint256 = true;
        bool f32unit = true, f32mant0 = true, f32small = true;
        bool bfunit = true, bfpow2 = true, bfsmall = true;
        bool neg32 = false, pos32 = false, negB = false, posB = false;
        #pragma unroll
        for (int j = 0; j < 4; j++) {
            int idx = lane + 32 * j;
            unsigned v = u[idx];
            lt16   &= (v < 16u);
            i64ids &= (idx & 1) ? (v == 0u) : (v < 16u);
            i64b   &= (idx & 1) ? (v == 0u) : (v < 256u);
            u32b   &= (v < 256u);
            float f = __uint_as_float(v);
            unsigned ex = (v >> 23) & 255u;
            bool fin = (ex != 255u);
            bool isint = fin && f >= 0.f && f == floorf(f);
            fint16  &= (isint && f < 16.f);
            fint256 &= (isint && f < 256.f);
            f32unit  &= (fin && f > 0.f && f < 1.f);
            f32mant0 &= ((v & 0x7FFFFFu) == 0u);
            f32small &= (fin && fabsf(f) < 100.f);
            neg32 |= (f < 0.f); pos32 |= (f > 0.f);
            unsigned hs[2] = { v >> 16, v & 0xFFFFu };
            #pragma unroll
            for (int q = 0; q < 2; q++) {
                unsigned h = hs[q];
                float fb = bfh(h);
                bool finB = (((h >> 7) & 255u) != 255u);
                bfunit  &= (finB && fb > 0.f && fb < 1.f);
                bfpow2  &= (finB && fb > 0.f && fb < 1.f && ((h & 127u) == 0u));
                bfsmall &= (finB && fabsf(fb) < 100.f);
                negB |= (fb < 0.f); posB |= (fb > 0.f);
            }
        }
        unsigned full = ~0u;
        lt16 = __all_sync(full, lt16);       i64ids = __all_sync(full, i64ids);
        i64b = __all_sync(full, i64b);       u32b = __all_sync(full, u32b);
        fint16 = __all_sync(full, fint16);   fint256 = __all_sync(full, fint256);
        f32unit = __all_sync(full, f32unit); f32mant0 = __all_sync(full, f32mant0);
        f32small = __all_sync(full, f32small);
        bfunit = __all_sync(full, bfunit);   bfpow2 = __all_sync(full, bfpow2);
        bfsmall = __all_sync(full, bfsmall);
        neg32 = __any_sync(full, neg32);     pos32 = __any_sync(full, pos32);
        negB = __any_sync(full, negB);       posB = __any_sync(full, posB);
        if (lane == 0) {
            int c, bf = 0;
            if (lt16)                         { c = 0; }
            else if (i64ids)                  { c = 0; bf = 2; }
            else if (fint16)                  { c = 0; bf = 3; }
            else if (i64b)                    { c = 4; bf = 5; }
            else if (u32b)                    { c = 4; bf = 3; }
            else if (fint256)                 { c = 4; bf = 4; }
            else if (f32unit && f32mant0)     { c = 2; }
            else if (bfunit && bfpow2)        { c = 2; bf = 1; }
            else if (f32unit)                 { c = 1; }
            else if (bfunit)                  { c = 1; bf = 1; }
            else if (f32small && neg32 && pos32) { c = 3; }
            else if (bfsmall && negB && posB)    { c = 3; bf = 1; }
            else                              { c = 4; bf = 0; }
            cls[w] = c; bff[w] = bf; ssz[w] = in.sz[w];
        }
    }
    __syncthreads();
    if (threadIdx.x == 0) {
        int ix = -1, ii = -1, iw = -1, s1 = -1, s2 = -1, p1 = -1, p2 = -1;
        for (int i = 0; i < in.n && i < 8; i++) {
            switch (cls[i]) {
                case 0: ii = i; break;
                case 1: iw = i; break;
                case 2: if (s1 < 0) s1 = i; else s2 = i; break;
                case 3: ix = i; break;
                case 4: if (p1 < 0) p1 = i; else p2 = i; break;
                default: break;
            }
        }
        if (ix >= 0 && ii >= 0 && iw >= 0 && s2 >= 0 && p2 >= 0) {
            int gus_i = s1, dsc_i = s2;
            if (ssz[s2] > ssz[s1]) { gus_i = s2; dsc_i = s1; }
            int guw_i = p1, dwn_i = p2;
            if (ssz[p2] > ssz[p1]) { guw_i = p2; dwn_i = p1; }
            g_rp[0] = in.p[ix];    g_bf[0] = bff[ix];
            g_rp[1] = in.p[ii];    g_bf[1] = bff[ii];
            g_rp[2] = in.p[iw];    g_bf[2] = bff[iw];
            g_rp[3] = in.p[guw_i]; g_bf[3] = bff[guw_i];
            g_rp[4] = in.p[gus_i]; g_bf[4] = bff[gus_i];
            g_rp[5] = in.p[dwn_i]; g_bf[5] = bff[dwn_i];
            g_rp[6] = in.p[dsc_i]; g_bf[6] = bff[dsc_i];
            g_bf[7] = bff[ix];
        } else {
            g_rp[0] = in.p[0]; g_rp[2] = in.p[1]; g_rp[1] = in.p[2];
            g_rp[3] = in.p[3]; g_rp[4] = in.p[4]; g_rp[5] = in.p[5]; g_rp[6] = in.p[6];
            for (int i = 0; i < 8; i++) g_bf[i] = 0;
        }
        for (int e = 0; e < NEXP; e++) g_cnt[e] = 0;
    }
}

// ---------------- helpers ----------------
__device__ __forceinline__ float ldf(const void* p, int bf, size_t i) {
    return bf ? __bfloat162float(((const __nv_bfloat16*)p)[i]) : ((const float*)p)[i];
}
__device__ __forceinline__ int ldid(const void* p, int flag, int i) {
    if (flag == 2) return (int)((const long long*)p)[i];
    if (flag == 3) return (int)((const float*)p)[i];
    return ((const int*)p)[i];
}
__device__ __forceinline__ unsigned ldb(const void* p, int m, size_t i) {
    switch (m) {
        case 3:  return ((const unsigned*)p)[i] & 255u;
        case 4:  return (unsigned)((const float*)p)[i] & 255u;
        case 5:  return (unsigned)(((const unsigned long long*)p)[i] & 255ull);
        default: return ((const uint8_t*)p)[i];
    }
}
__device__ __forceinline__ float fp4v(unsigned n) {
    float m = (float)((0xC8643210u >> ((n & 7u) * 4)) & 15u);
    return (n & 8u) ? -m : m;
}
__device__ __forceinline__ uint32_t pack_hf2(float a, float b) {
    __half2 h = __floats2half2_rn(a, b);
    return *(uint32_t*)&h;
}
__device__ __forceinline__ uint32_t s2u(const void* p) {
    uint32_t a;
    asm("{ .reg .u64 t; cvta.to.shared.u64 t, %1; cvt.u32.u64 %0, t; }" : "=r"(a) : "l"(p));
    return a;
}
__device__ __forceinline__ void cp16(uint32_t saddr, const void* gaddr) {
    asm volatile("cp.async.cg.shared.global [%0], [%1], 16;" :: "r"(saddr), "l"(gaddr) : "memory");
}
__device__ __forceinline__ void cp_commit() {
    asm volatile("cp.async.commit_group;" ::: "memory");
}
template <int N>
__device__ __forceinline__ void cp_wait() {
    asm volatile("cp.async.wait_group %0;" :: "n"(N) : "memory");
}

// ---------------- one-time weight dequant to fp16 (exact) ----------------
__global__ void k_deq_gu() {
    size_t i = (size_t)blockIdx.x * 256 + threadIdx.x;
    const void* W = g_rp[3]; const int m = g_bf[3];
    const void* S = g_rp[4]; const int sbf = g_bf[4];
    size_t row = i >> 8;
    unsigned cb = ((unsigned)i & 255u) * 4u;
    float sc = ldf(S, sbf, row * 64 + (cb >> 4)) * 0.5f;
    float v[8];
    #pragma unroll
    for (int q = 0; q < 4; q++) {
        unsigned by = ldb(W, m, row * 1024 + cb + q);
        v[2 * q]     = fp4v(by & 15u) * sc;
        v[2 * q + 1] = fp4v(by >> 4)  * sc;
    }
    uint4 o = make_uint4(pack_hf2(v[0], v[1]), pack_hf2(v[2], v[3]),
                         pack_hf2(v[4], v[5]), pack_hf2(v[6], v[7]));
    ((uint4*)g_wgu)[i] = o;
}
__global__ void k_deq_dn() {
    size_t i = (size_t)blockIdx.x * 256 + threadIdx.x;
    const void* W = g_rp[5]; const int m = g_bf[5];
    const void* S = g_rp[6]; const int sbf = g_bf[6];
    size_t row = i >> 7;
    unsigned cb = ((unsigned)i & 127u) * 4u;
    float sc = ldf(S, sbf, row * 32 + (cb >> 4)) * 0.5f;
    float v[8];
    #pragma unroll
    for (int q = 0; q < 4; q++) {
        unsigned by = ldb(W, m, row * 512 + cb + q);
        v[2 * q]     = fp4v(by & 15u) * sc;
        v[2 * q + 1] = fp4v(by >> 4)  * sc;
    }
    uint4 o = make_uint4(pack_hf2(v[0], v[1]), pack_hf2(v[2], v[3]),
                         pack_hf2(v[4], v[5]), pack_hf2(v[6], v[7]));
    ((uint4*)g_wdn)[i] = o;
}

// ---------------- convert x to fp16 ----------------
__global__ void k_cvt_x() {
    size_t g = (size_t)blockIdx.x * 256 + threadIdx.x;   // 4 elements per thread
    const void* xp = g_rp[0]; const int xbf = g_bf[0];
    size_t b = g * 4;
    uint2 o;
    o.x = pack_hf2(ldf(xp, xbf, b + 0), ldf(xp, xbf, b + 1));
    o.y = pack_hf2(ldf(xp, xbf, b + 2), ldf(xp, xbf, b + 3));
    ((uint2*)g_x)[g] = o;
}

// ---------------- routing ----------------
__global__ void k_route() {
    int s = blockIdx.x * 256 + threadIdx.x;
    if (s >= NSLOT) return;
    int e = ldid(g_rp[1], g_bf[1], s) & (NEXP - 1);
    int p = atomicAdd(&g_cnt[e], 1);
    g_slot[e * NSLOT + p] = s;
    g_wt[e * NSLOT + p]   = ldf(g_rp[2], g_bf[2], s);
}

// =====================================================================
// wmma fp16 grouped GEMMs, single pass, 4-stage cp.async pipeline, BK=32.
// CTA tile 128x128, 4 warps (2x2), warp tile 64x64.
// Stage: sA|sB, each 128x40 half (data 128x32) = 10240 B -> 20480/stage.
// 4 stages = 81920 B dsmem => 2 CTAs/SM.
// =====================================================================
extern __shared__ char dsm[];
#define LDA 40
#define LDS_ 132
#define ARR_B 10240
#define STAGE_B 20480

// GEMM1: per (64-f tile, 128-slot tile, expert): gate|up, fused SwiGLU
__global__ void __launch_bounds__(128, 2) k_mma1() {
    const int e = blockIdx.z, cnt = g_cnt[e];
    const int m0 = blockIdx.y * 128;
    if (m0 >= cnt) return;
    const int n0 = blockIdx.x * 64;

    float* S = (float*)dsm;
    __shared__ int sSlot[128], sTok[128];
    __shared__ float sWt[128];

    const int tid = threadIdx.x, wid = tid >> 5;
    {
        int m = m0 + tid;
        int sl = (m < cnt) ? g_slot[e * NSLOT + m] : g_slot[e * NSLOT];
        sSlot[tid] = sl; sTok[tid] = sl >> 2;
        sWt[tid] = (m < cnt) ? g_wt[e * NSLOT + m] : 0.f;
    }
    __syncthreads();

    // copy descriptors: 4 chunks of 16B per array per stage (128x32 halves)
    const uint32_t smBase = s2u(dsm);
    const __half* BGU = g_wgu + (size_t)e * 2 * F_DIM * H_DIM;
    const __half* gA[4];
    const __half* gB[4];
    uint32_t sOff[4];
    #pragma unroll
    for (int q = 0; q < 4; q++) {
        int i = tid + q * 128;
        int r = i >> 2, c = (i & 3) * 8;
        gA[q] = g_x + (size_t)sTok[r] * H_DIM + c;
        int rowW = (r < 64) ? (n0 + r) : (F_DIM + n0 + r - 64);
        gB[q] = BGU + (size_t)rowW * H_DIM + c;
        sOff[q] = (uint32_t)(r * LDA + c) * 2u;
    }

    #define ISSUE1(kc) do { \
        uint32_t sb = smBase + (uint32_t)((kc) & 3) * STAGE_B; \
        int koff = (kc) * 32; \
        _Pragma("unroll") \
        for (int q = 0; q < 4; q++) { \
            cp16(sb + sOff[q],          gA[q] + koff); \
            cp16(sb + ARR_B + sOff[q],  gB[q] + koff); \
        } \
        cp_commit(); \
    } while (0)

    const int wm = (wid & 1) * 64, wn = (wid >> 1) * 64;
    wmma::fragment<wmma::accumulator, 16, 16, 16, float> acc[4][4];
    #pragma unroll
    for (int i = 0; i < 4; i++)
        #pragma unroll
        for (int j = 0; j < 4; j++) wmma::fill_fragment(acc[i][j], 0.f);

    const int NK = H_DIM / 32;
    ISSUE1(0); ISSUE1(1); ISSUE1(2);
    for (int kc = 0; kc < NK; kc++) {
        if (kc + 3 < NK)      { ISSUE1(kc + 3); cp_wait<3>(); }
        else if (kc + 2 < NK) { cp_wait<2>(); }
        else if (kc + 1 < NK) { cp_wait<1>(); }
        else                  { cp_wait<0>(); }
        __syncthreads();
        const char* stg = dsm + (size_t)(kc & 3) * STAGE_B;
        const __half* sA = (const __half*)stg;
        const __half* sB = (const __half*)(stg + ARR_B);
        #pragma unroll
        for (int ks = 0; ks < 2; ks++) {
            wmma::fragment<wmma::matrix_b, 16, 16, 16, __half, wmma::col_major> bf[4];
            #pragma unroll
            for (int nf = 0; nf < 4; nf++)
                wmma::load_matrix_sync(bf[nf], sB + (wn + nf * 16) * LDA + ks * 16, LDA);
            #pragma unroll
            for (int mf = 0; mf < 4; mf++) {
                wmma::fragment<wmma::matrix_a, 16, 16, 16, __half, wmma::row_major> af;
                wmma::load_matrix_sync(af, sA + (wm + mf * 16) * LDA + ks * 16, LDA);
                #pragma unroll
                for (int nf = 0; nf < 4; nf++)
                    wmma::mma_sync(acc[mf][nf], af, bf[nf], acc[mf][nf]);
            }
        }
        __syncthreads();
    }
    #pragma unroll
    for (int mf = 0; mf < 4; mf++)
        #pragma unroll
        for (int nf = 0; nf < 4; nf++)
            wmma::store_matrix_sync(S + (wm + mf * 16) * LDS_ + wn + nf * 16,
                                    acc[mf][nf], LDS_, wmma::mem_row_major);
    __syncthreads();

    // SwiGLU epilogue: cols [0,64)=gate, [64,128)=up → act fp16
    {
        const int row = tid;
        if (m0 + row < cnt) {
            const float wt = sWt[row];
            const size_t arow = (size_t)sSlot[row] * F_DIM + n0;
            #pragma unroll
            for (int q = 0; q < 8; q++) {      // 8 halves per uint4
                uint32_t hw[4];
                #pragma unroll
                for (int r2 = 0; r2 < 4; r2++) {
                    int j = q * 8 + r2 * 2;
                    float g0 = S[row * LDS_ + j],     u0 = S[row * LDS_ + 64 + j];
                    float g1 = S[row * LDS_ + j + 1], u1 = S[row * LDS_ + 65 + j];
                    float v0 = g0 * (1.f / (1.f + __expf(-g0))) * u0 * wt;
                    float v1 = g1 * (1.f / (1.f + __expf(-g1))) * u1 * wt;
                    hw[r2] = pack_hf2(v0, v1);
                }
                ((uint4*)(g_act + arow))[q] = make_uint4(hw[0], hw[1], hw[2], hw[3]);
            }
        }
    }
}

// GEMM2: per (128-h tile, 128-slot tile, expert): part = act @ Wd^T
__global__ void __launch_bounds__(128, 2) k_mma2() {
    const int e = blockIdx.z, cnt = g_cnt[e];
    const int m0 = blockIdx.y * 128;
    if (m0 >= cnt) return;
    const int n0 = blockIdx.x * 128;

    float* S = (float*)dsm;
    __shared__ int sSlot[128];

    const int tid = threadIdx.x, wid = tid >> 5;
    {
        int m = m0 + tid;
        sSlot[tid] = (m < cnt) ? g_slot[e * NSLOT + m] : g_slot[e * NSLOT];
    }
    __syncthreads();

    const uint32_t smBase = s2u(dsm);
    const __half* BW = g_wdn + (size_t)e * H_DIM * F_DIM;
    const __half* gA[4];
    const __half* gB[4];
    uint32_t sOff[4];
    #pragma unroll
    for (int q = 0; q < 4; q++) {
        int i = tid + q * 128;
        int r = i >> 2, c = (i & 3) * 8;
        gA[q] = g_act + (size_t)sSlot[r] * F_DIM + c;
        gB[q] = BW + (size_t)(n0 + r) * F_DIM + c;
        sOff[q] = (uint32_t)(r * LDA + c) * 2u;
    }

    #define ISSUE2(kc) do { \
        uint32_t sb = smBase + (uint32_t)((kc) & 3) * STAGE_B; \
        int koff = (kc) * 32; \
        _Pragma("unroll") \
        for (int q = 0; q < 4; q++) { \
            cp16(sb + sOff[q],          gA[q] + koff); \
            cp16(sb + ARR_B + sOff[q],  gB[q] + koff); \
        } \
        cp_commit(); \
    } while (0)

    const int wm = (wid & 1) * 64, wn = (wid >> 1) * 64;
    wmma::fragment<wmma::accumulator, 16, 16, 16, float> acc[4][4];
    #pragma unroll
    for (int i = 0; i < 4; i++)
        #pragma unroll
        for (int j = 0; j < 4; j++) wmma::fill_fragment(acc[i][j], 0.f);

    const int NK = F_DIM / 32;
    ISSUE2(0); ISSUE2(1); ISSUE2(2);
    for (int kc = 0; kc < NK; kc++) {
        if (kc + 3 < NK)      { ISSUE2(kc + 3); cp_wait<3>(); }
        else if (kc + 2 < NK) { cp_wait<2>(); }
        else if (kc + 1 < NK) { cp_wait<1>(); }
        else                  { cp_wait<0>(); }
        __syncthreads();
        const char* stg = dsm + (size_t)(kc & 3) * STAGE_B;
        const __half* sA = (const __half*)stg;
        const __half* sB = (const __half*)(stg + ARR_B);
        #pragma unroll
        for (int ks = 0; ks < 2; ks++) {
            wmma::fragment<wmma::matrix_b, 16, 16, 16, __half, wmma::col_major> bf[4];
            #pragma unroll
            for (int nf = 0; nf < 4; nf++)
                wmma::load_matrix_sync(bf[nf], sB + (wn + nf * 16) * LDA + ks * 16, LDA);
            #pragma unroll
            for (int mf = 0; mf < 4; mf++) {
                wmma::fragment<wmma::matrix_a, 16, 16, 16, __half, wmma::row_major> af;
                wmma::load_matrix_sync(af, sA + (wm + mf * 16) * LDA + ks * 16, LDA);
                #pragma unroll
                for (int nf = 0; nf < 4; nf++)
                    wmma::mma_sync(acc[mf][nf], af, bf[nf], acc[mf][nf]);
            }
        }
        __syncthreads();
    }
    #pragma unroll
    for (int mf = 0; mf < 4; mf++)
        #pragma unroll
        for (int nf = 0; nf < 4; nf++)
            wmma::store_matrix_sync(S + (wm + mf * 16) * LDS_ + wn + nf * 16,
                                    acc[mf][nf], LDS_, wmma::mem_row_major);
    __syncthreads();

    {
        const int row = tid;
        if (m0 + row < cnt) {
            const size_t prow = (size_t)sSlot[row] * H_DIM + n0;
            #pragma unroll
            for (int q = 0; q < 32; q++) {
                float4 o = make_float4(S[row * LDS_ + q * 4],     S[row * LDS_ + q * 4 + 1],
                                       S[row * LDS_ + q * 4 + 2], S[row * LDS_ + q * 4 + 3]);
                ((float4*)(g_part + prow))[q] = o;
            }
        }
    }
}

// deterministic 4-way reduce; dtype-flexible output
__global__ void k_reduce(void* __restrict__ outv) {
    int idx = blockIdx.x * 256 + threadIdx.x;
    int t = idx / (H_DIM / 4);
    int c = idx % (H_DIM / 4);
    const float4* p = (const float4*)g_part;
    float4 a = p[(size_t)(t * 4 + 0) * (H_DIM / 4) + c];
    float4 b = p[(size_t)(t * 4 + 1) * (H_DIM / 4) + c];
    float4 d = p[(size_t)(t * 4 + 2) * (H_DIM / 4) + c];
    float4 e = p[(size_t)(t * 4 + 3) * (H_DIM / 4) + c];
    float s0 = a.x + b.x + d.x + e.x, s1 = a.y + b.y + d.y + e.y;
    float s2 = a.z + b.z + d.z + e.z, s3 = a.w + b.w + d.w + e.w;
    if (g_bf[7]) {
        __nv_bfloat16* ob = (__nv_bfloat16*)outv;
        size_t base = (size_t)t * H_DIM + c * 4;
        ob[base + 0] = __float2bfloat16(s0);
        ob[base + 1] = __float2bfloat16(s1);
        ob[base + 2] = __float2bfloat16(s2);
        ob[base + 3] = __float2bfloat16(s3);
    } else {
        ((float4*)outv)[(size_t)t * (H_DIM / 4) + c] = make_float4(s0, s1, s2, s3);
    }
}

extern "C" void kernel_launch(void* const* d_in, const int* in_sizes, int n_in,
                              void* d_out, int out_size) {
    InPtrs in;
    int n = (n_in < 8) ? n_in : 8;
    for (int i = 0; i < 8; i++) {
        in.p[i]  = (i < n) ? d_in[i] : nullptr;
        in.sz[i] = (i < n) ? (long long)in_sizes[i] : 0;
    }
    in.n = n;

    const int DSMEM = 4 * STAGE_B;   // 81920 (covers 67584 epilogue buffer)
    cudaFuncSetAttribute(k_mma1, cudaFuncAttributeMaxDynamicSharedMemorySize, DSMEM);
    cudaFuncSetAttribute(k_mma2, cudaFuncAttributeMaxDynamicSharedMemorySize, DSMEM);

    k_resolve<<<1, 256>>>(in);
    k_deq_gu<<<(NEXP * 2 * F_DIM * (H_DIM / 2) / 4) / 256, 256>>>();
    k_deq_dn<<<(NEXP * H_DIM * (F_DIM / 2) / 4) / 256, 256>>>();
    k_cvt_x<<<(T_TOK * H_DIM / 4) / 256, 256>>>();
    k_route<<<NSLOT / 256, 256>>>();
    k_mma1<<<dim3(F_DIM / 64, NSLOT / 128, NEXP), 128, DSMEM>>>();
    k_mma2<<<dim3(H_DIM / 128, NSLOT / 128, NEXP), 128, DSMEM>>>();
    k_reduce<<<(T_TOK * H_DIM / 4) / 256, 256>>>(d_out);
}